// round 3
// baseline (speedup 1.0000x reference)
#include <cuda_runtime.h>
#include <cstdint>
#include <math.h>

// ---------------- problem constants ----------------
#define T_STEPS 512
#define BATCH   64
#define EMB_D   400
#define HID_D   1152
#define M_ROWS  (T_STEPS * BATCH)   // 32768

// ---------------- scratch (static device memory; no cudaMalloc allowed) ----
__device__ float g_act0[(size_t)M_ROWS * HID_D];        // 151 MB
__device__ float g_act1[(size_t)M_ROWS * HID_D];        // 151 MB
__device__ float g_xw[(size_t)M_ROWS * 4 * HID_D];      // 604 MB
__device__ float g_h[2][BATCH * HID_D];                 // double-buffered hidden state
__device__ unsigned int g_arrive;                       // grid barrier counter

// ---------------- packed f32x2 helpers ----------------
__device__ __forceinline__ unsigned long long pack2(float lo, float hi) {
    unsigned long long r;
    asm("mov.b64 %0, {%1, %2};" : "=l"(r) : "f"(lo), "f"(hi));
    return r;
}
__device__ __forceinline__ void unpack2(unsigned long long v, float& lo, float& hi) {
    asm("mov.b64 {%0, %1}, %2;" : "=f"(lo), "=f"(hi) : "l"(v));
}
__device__ __forceinline__ unsigned long long fma2(unsigned long long a,
                                                   unsigned long long b,
                                                   unsigned long long c) {
    unsigned long long d;
    asm("fma.rn.f32x2 %0, %1, %2, %3;" : "=l"(d) : "l"(a), "l"(b), "l"(c));
    return d;
}

// ---------------- helpers ----------------
__device__ __forceinline__ float sigm(float x) { return 1.0f / (1.0f + expf(-x)); }

__device__ __forceinline__ void grid_barrier(int nctas, unsigned int target) {
    __syncthreads();
    if (threadIdx.x == 0) {
        __threadfence();
        atomicAdd(&g_arrive, 1u);
        unsigned int v;
        do {
            asm volatile("ld.acquire.gpu.u32 %0, [%1];" : "=r"(v) : "l"(&g_arrive) : "memory");
        } while (v < target);
    }
    __syncthreads();
}

__global__ void reset_bar_kernel() { g_arrive = 0u; }

// ---------------- embedding gather ----------------
__global__ void embed_kernel(const int* __restrict__ x, const float* __restrict__ emb,
                             float* __restrict__ out) {
    const int m = blockIdx.x;                 // 0 .. T*B-1
    const int tok = x[m];
    const float4* src = (const float4*)(emb + (size_t)tok * EMB_D);
    float4* dst = (float4*)(out + (size_t)m * EMB_D);
    for (int i = threadIdx.x; i < EMB_D / 4; i += blockDim.x) dst[i] = src[i];
}

// ---------------- input projection: out[M][N] = A[M][K] @ W[N][K]^T + (bih+bhh) ----
__global__ void __launch_bounds__(256)
gemm_xw_kernel(const float* __restrict__ A, const float* __restrict__ W,
               const float* __restrict__ bih, const float* __restrict__ bhh,
               float* __restrict__ out, int N, int K) {
    __shared__ float sA[8][128];
    __shared__ float sB[8][128];
    const int tid = threadIdx.x;
    const int tx = tid & 15;
    const int ty = tid >> 4;
    const int m0 = blockIdx.y * 128;
    const int n0 = blockIdx.x * 128;

    const int lrow = tid >> 1;
    const int lkq  = (tid & 1) * 4;
    const float* Ap = A + (size_t)(m0 + lrow) * K + lkq;
    const int nrow = n0 + lrow;
    const float* Wp = W + (size_t)nrow * K + lkq;
    const bool wok = (nrow < N);

    unsigned long long acc2[8][4];
#pragma unroll
    for (int i = 0; i < 8; ++i)
#pragma unroll
        for (int jp = 0; jp < 4; ++jp) acc2[i][jp] = 0ull;

    for (int kt = 0; kt < K; kt += 8) {
        float4 av = *(const float4*)(Ap + kt);
        float4 wv = wok ? *(const float4*)(Wp + kt) : make_float4(0.f, 0.f, 0.f, 0.f);
        sA[lkq + 0][lrow] = av.x; sA[lkq + 1][lrow] = av.y;
        sA[lkq + 2][lrow] = av.z; sA[lkq + 3][lrow] = av.w;
        sB[lkq + 0][lrow] = wv.x; sB[lkq + 1][lrow] = wv.y;
        sB[lkq + 2][lrow] = wv.z; sB[lkq + 3][lrow] = wv.w;
        __syncthreads();
#pragma unroll
        for (int k = 0; k < 8; ++k) {
            float ra[8];
            *(float4*)&ra[0] = *(const float4*)&sA[k][ty * 8];
            *(float4*)&ra[4] = *(const float4*)&sA[k][ty * 8 + 4];
            ulonglong2 rb01 = *(const ulonglong2*)&sB[k][tx * 8];
            ulonglong2 rb23 = *(const ulonglong2*)&sB[k][tx * 8 + 4];
            unsigned long long rb2[4] = {rb01.x, rb01.y, rb23.x, rb23.y};
#pragma unroll
            for (int i = 0; i < 8; ++i) {
                const unsigned long long ai = pack2(ra[i], ra[i]);
#pragma unroll
                for (int jp = 0; jp < 4; ++jp)
                    acc2[i][jp] = fma2(ai, rb2[jp], acc2[i][jp]);
            }
        }
        __syncthreads();
    }

    float bias[8];
#pragma unroll
    for (int j = 0; j < 8; ++j) {
        const int n = n0 + tx * 8 + j;
        bias[j] = (n < N) ? (__ldg(bih + n) + __ldg(bhh + n)) : 0.0f;
    }
#pragma unroll
    for (int i = 0; i < 8; ++i) {
        float vals[8];
#pragma unroll
        for (int jp = 0; jp < 4; ++jp) unpack2(acc2[i][jp], vals[2 * jp], vals[2 * jp + 1]);
        float* orow = out + (size_t)(m0 + ty * 8 + i) * N + n0 + tx * 8;
#pragma unroll
        for (int j = 0; j < 8; ++j)
            if (n0 + tx * 8 + j < N) orow[j] = vals[j] + bias[j];
    }
}

// ---------------- persistent recurrent LSTM layer (v2) ----------------
// Per CTA: NJ hidden units -> R = 4*NJ gate rows, all 64 batches.
// Split-k x2 across thread halves. Per thread: 2 rows x 8 batches.
// W_hh cached k-major in SMEM; h staged in double-buffered 32-k chunks with
// prefetch into registers (L2 latency hidden behind FFMA2 compute).
template <int H, int NJ>
__global__ void __launch_bounds__(NJ * 32, 1)
lstm_rec2_kernel(const float* __restrict__ xw, const float* __restrict__ Whh,
                 float* __restrict__ out, int nctas) {
    constexpr int R = 4 * NJ;                  // 32 / 16
    constexpr int THREADS = NJ * 32;           // 256 / 128
    constexpr int HT = THREADS / 2;            // threads per k-half
    constexpr int HALFK = H / 2;               // 576 / 200
    constexpr int NCHUNK = (HALFK + 31) / 32;  // 18 / 7
    constexpr int KPAD = NCHUNK * 32;
    constexpr int KPT = (32 * 64) / HT;        // floats staged per thread (16/32)
    constexpr int F4 = KPT / 4;

    extern __shared__ float sm[];
    float* sWT   = sm;                          // [2][KPAD][R]  k-major, zero-padded
    float* sA    = sWT + 2 * KPAD * R;          // [2 half][2 buf][32][64]
    float* sC    = sA + 2 * 2 * 32 * 64;        // [64][R] gate exchange
    float* sCell = sC + 64 * R;                 // [64*NJ]

    const int tid = threadIdx.x;
    const int j0  = blockIdx.x * NJ;
    const int z   = tid / HT;            // k-half
    const int lt  = tid - z * HT;
    const int rg  = lt >> 3;             // row-pair id -> rows rg*2, rg*2+1
    const int bg  = lt & 7;              // batch group of 8

    // ---- init: W_hh slice transposed (k-major) into SMEM, zero-padded k ----
    for (int idx = tid; idx < 2 * KPAD * R; idx += THREADS) {
        const int zz  = idx / (KPAD * R);
        const int rem = idx - zz * (KPAD * R);
        const int kl  = rem / R;
        const int r   = rem - kl * R;
        float v = 0.0f;
        if (kl < HALFK) {
            const int grow = (r / NJ) * H + j0 + (r % NJ);
            v = Whh[(size_t)grow * H + zz * HALFK + kl];
        }
        sWT[idx] = v;
    }
    for (int i = tid; i < 64 * NJ; i += THREADS) {
        sCell[i] = 0.0f;
        const int b = i / NJ, u = i - b * NJ;
        g_h[0][b * H + j0 + u] = 0.0f;
    }
    unsigned int ep = 1;
    grid_barrier(nctas, ep * (unsigned)nctas); ++ep;

    // staging source mapping: thread stages batch sb, k-range [skb, skb+KPT)
    const int sb  = lt & 63;
    const int skb = (lt >> 6) * KPT;

    const float* sAz = sA + z * (2 * 32 * 64);
    const float* sWz = sWT + z * (KPAD * R);
    const int g  = (rg * 2) / NJ;        // gate of this thread's row pair
    const int u0 = (rg * 2) % NJ;

    for (int t = 0; t < T_STEPS; ++t) {
        const float* hbuf = g_h[t & 1];
        float* hnext = g_h[1 - (t & 1)];

        // prefetch xw for this thread's outputs (overlaps with chunk loop)
        float2 xwv[8];
        if (z == 0) {
            const float* xwbase = xw + (size_t)t * BATCH * (4 * H) + g * H + j0 + u0;
#pragma unroll
            for (int q = 0; q < 8; ++q)
                xwv[q] = __ldg((const float2*)(xwbase + (size_t)(bg * 8 + q) * (4 * H)));
        }

        // prefetch h chunk 0
        float4 pf[F4];
#pragma unroll
        for (int j = 0; j < F4; ++j) {
            const int kl = skb + j * 4;
            pf[j] = (kl < HALFK)
                ? __ldcg((const float4*)(hbuf + (size_t)sb * H + z * HALFK + kl))
                : make_float4(0.f, 0.f, 0.f, 0.f);
        }

        unsigned long long acc[8];       // [rw(2)][bp(4)] -> rw*4+bp, pair over batches
#pragma unroll
        for (int i = 0; i < 8; ++i) acc[i] = 0ull;

        for (int ci = 0; ci < NCHUNK; ++ci) {
            // stage prefetched chunk into SMEM
            float* dst = (float*)sAz + (ci & 1) * (32 * 64);
#pragma unroll
            for (int j = 0; j < F4; ++j) {
                const int kk = skb + j * 4;
                dst[(kk + 0) * 64 + sb] = pf[j].x;
                dst[(kk + 1) * 64 + sb] = pf[j].y;
                dst[(kk + 2) * 64 + sb] = pf[j].z;
                dst[(kk + 3) * 64 + sb] = pf[j].w;
            }
            __syncthreads();
            // prefetch next chunk
            if (ci + 1 < NCHUNK) {
                const int klbase = (ci + 1) * 32 + skb;
#pragma unroll
                for (int j = 0; j < F4; ++j) {
                    const int kl = klbase + j * 4;
                    pf[j] = (kl < HALFK)
                        ? __ldcg((const float4*)(hbuf + (size_t)sb * H + z * HALFK + kl))
                        : make_float4(0.f, 0.f, 0.f, 0.f);
                }
            }
            // compute current chunk
            const float* asrc = sAz + (ci & 1) * (32 * 64) + bg * 8;
            const float* wsrc = sWz + ci * 32 * R + rg * 2;
#pragma unroll 8
            for (int kk = 0; kk < 32; ++kk) {
                const ulonglong2 av01 = *(const ulonglong2*)(asrc + kk * 64);
                const ulonglong2 av23 = *(const ulonglong2*)(asrc + kk * 64 + 4);
                const float2 wv = *(const float2*)(wsrc + kk * R);
                const unsigned long long w0 = pack2(wv.x, wv.x);
                const unsigned long long w1 = pack2(wv.y, wv.y);
                acc[0] = fma2(w0, av01.x, acc[0]);
                acc[1] = fma2(w0, av01.y, acc[1]);
                acc[2] = fma2(w0, av23.x, acc[2]);
                acc[3] = fma2(w0, av23.y, acc[3]);
                acc[4] = fma2(w1, av01.x, acc[4]);
                acc[5] = fma2(w1, av01.y, acc[5]);
                acc[6] = fma2(w1, av23.x, acc[6]);
                acc[7] = fma2(w1, av23.y, acc[7]);
            }
        }

        // ---- split-k reduction + xw add through sC ----
        if (z == 1) {
#pragma unroll
            for (int bp = 0; bp < 4; ++bp) {
                float a0lo, a0hi, a1lo, a1hi;
                unpack2(acc[bp], a0lo, a0hi);
                unpack2(acc[4 + bp], a1lo, a1hi);
                const int b0 = bg * 8 + bp * 2;
                *(float2*)(sC + b0 * R + rg * 2) = make_float2(a0lo, a1lo);
                *(float2*)(sC + (b0 + 1) * R + rg * 2) = make_float2(a0hi, a1hi);
            }
        }
        __syncthreads();
        if (z == 0) {
#pragma unroll
            for (int bp = 0; bp < 4; ++bp) {
                float a0lo, a0hi, a1lo, a1hi;
                unpack2(acc[bp], a0lo, a0hi);
                unpack2(acc[4 + bp], a1lo, a1hi);
                const int b0 = bg * 8 + bp * 2;
                float2 p0 = *(const float2*)(sC + b0 * R + rg * 2);
                float2 p1 = *(const float2*)(sC + (b0 + 1) * R + rg * 2);
                p0.x += a0lo + xwv[bp * 2].x;     p0.y += a1lo + xwv[bp * 2].y;
                p1.x += a0hi + xwv[bp * 2 + 1].x; p1.y += a1hi + xwv[bp * 2 + 1].y;
                *(float2*)(sC + b0 * R + rg * 2) = p0;
                *(float2*)(sC + (b0 + 1) * R + rg * 2) = p1;
            }
        }
        __syncthreads();

        // ---- cell/hidden update ----
#pragma unroll
        for (int rep = 0; rep < 2; ++rep) {
            const int i = tid + rep * THREADS;
            if (i < 64 * NJ) {
                const int b = i / NJ, u = i - b * NJ;
                const float gi = sC[b * R + 0 * NJ + u];
                const float gf = sC[b * R + 1 * NJ + u];
                const float gg = sC[b * R + 2 * NJ + u];
                const float go = sC[b * R + 3 * NJ + u];
                float c = sCell[i];
                c = sigm(gf) * c + sigm(gi) * tanhf(gg);
                sCell[i] = c;
                const float hv = sigm(go) * tanhf(c);
                hnext[b * H + j0 + u] = hv;
                out[((size_t)t * BATCH + b) * H + j0 + u] = hv;
            }
        }
        grid_barrier(nctas, ep * (unsigned)nctas); ++ep;
    }
}

// ---------------- launch ----------------
extern "C" void kernel_launch(void* const* d_in, const int* in_sizes, int n_in,
                              void* d_out, int out_size) {
    (void)in_sizes; (void)n_in; (void)out_size;
    const int*   x    = (const int*)d_in[0];
    const float* emb  = (const float*)d_in[1];
    const float* Wih0 = (const float*)d_in[2];
    const float* Whh0 = (const float*)d_in[3];
    const float* bih0 = (const float*)d_in[4];
    const float* bhh0 = (const float*)d_in[5];
    const float* Wih1 = (const float*)d_in[6];
    const float* Whh1 = (const float*)d_in[7];
    const float* bih1 = (const float*)d_in[8];
    const float* bhh1 = (const float*)d_in[9];
    const float* Wih2 = (const float*)d_in[10];
    const float* Whh2 = (const float*)d_in[11];
    const float* bih2 = (const float*)d_in[12];
    const float* bhh2 = (const float*)d_in[13];
    float* out = (float*)d_out;

    float *act0, *act1, *xw;
    cudaGetSymbolAddress((void**)&act0, g_act0);
    cudaGetSymbolAddress((void**)&act1, g_act1);
    cudaGetSymbolAddress((void**)&xw, g_xw);

    // SMEM sizes for the two recurrence configs
    const size_t SMEM_BIG = (size_t)(2 * ((HID_D / 2 + 31) / 32 * 32) * 32
                                     + 2 * 2 * 32 * 64 + 64 * 32 + 64 * 8) * sizeof(float);
    const size_t SMEM_SMALL = (size_t)(2 * ((EMB_D / 2 + 31) / 32 * 32) * 16
                                       + 2 * 2 * 32 * 64 + 64 * 16 + 64 * 4) * sizeof(float);
    cudaFuncSetAttribute((const void*)lstm_rec2_kernel<HID_D, 8>,
                         cudaFuncAttributeMaxDynamicSharedMemorySize, (int)SMEM_BIG);
    cudaFuncSetAttribute((const void*)lstm_rec2_kernel<EMB_D, 4>,
                         cudaFuncAttributeMaxDynamicSharedMemorySize, (int)SMEM_SMALL);

    // embedding
    embed_kernel<<<M_ROWS, 128>>>(x, emb, act0);

    // layer 0: din=400, H=1152
    gemm_xw_kernel<<<dim3(36, 256), 256>>>(act0, Wih0, bih0, bhh0, xw, 4 * HID_D, EMB_D);
    reset_bar_kernel<<<1, 1>>>();
    lstm_rec2_kernel<HID_D, 8><<<144, 256, SMEM_BIG>>>(xw, Whh0, act1, 144);

    // layer 1: din=1152, H=1152
    gemm_xw_kernel<<<dim3(36, 256), 256>>>(act1, Wih1, bih1, bhh1, xw, 4 * HID_D, HID_D);
    reset_bar_kernel<<<1, 1>>>();
    lstm_rec2_kernel<HID_D, 8><<<144, 256, SMEM_BIG>>>(xw, Whh1, act0, 144);

    // layer 2: din=1152, H=400
    gemm_xw_kernel<<<dim3(13, 256), 256>>>(act0, Wih2, bih2, bhh2, xw, 4 * EMB_D, HID_D);
    reset_bar_kernel<<<1, 1>>>();
    lstm_rec2_kernel<EMB_D, 4><<<100, 128, SMEM_SMALL>>>(xw, Whh2, out, 100);
}